// round 1
// baseline (speedup 1.0000x reference)
#include <cuda_runtime.h>
#include <math.h>

#define BB 4
#define SS 2048
#define DM 768
#define NH 12
#define HD 64
#define DM3 2304
#define MR (BB*SS)   // 8192 rows

// ---------------- scratch (device globals; no allocation allowed) ----------------
__device__ float g_qkv[MR*DM3];   // 75.5 MB : [b][s][3*DM]  (q | k | v, head-major inside)
__device__ float g_av [MR*DM];    // 25 MB   : attention output
__device__ float g_t1 [MR*DM];    // 25 MB   : GEMM temporaries
__device__ float g_hid[MR*DM];    // 25 MB   : hidden after norm1

// ---------------- GEMM:  C[M,N] = A[M,K] @ W[K,N] + bias[N] ----------------
// 64x64 tile, BK=32, 256 threads, 4x4 register blocking.
template<int N, int K>
__global__ __launch_bounds__(256)
void gemm_bias(const float* __restrict__ A, const float* __restrict__ W,
               const float* __restrict__ bias, float* __restrict__ C)
{
    __shared__ float As[32][64];   // transposed: As[k][m]
    __shared__ float Bs[32][64];   // Bs[k][n]

    const int tid = threadIdx.x;
    const int tx  = tid & 15;      // n group
    const int ty  = tid >> 4;      // m group
    const int m0  = blockIdx.y * 64;
    const int n0  = blockIdx.x * 64;

    float acc[4][4] = {};

    for (int kt = 0; kt < K; kt += 32) {
        // load A tile 64x32 (transposed into smem)
        #pragma unroll
        for (int l = 0; l < 2; l++) {
            int idx = tid + l * 256;          // 0..511
            int row = idx >> 3;               // 0..63
            int c4  = (idx & 7) << 2;         // 0..28
            float4 a = *(const float4*)&A[(size_t)(m0 + row) * K + kt + c4];
            As[c4+0][row] = a.x; As[c4+1][row] = a.y;
            As[c4+2][row] = a.z; As[c4+3][row] = a.w;
        }
        // load B tile 32x64
        #pragma unroll
        for (int l = 0; l < 2; l++) {
            int idx = tid + l * 256;
            int row = idx >> 4;               // 0..31
            int c4  = (idx & 15) << 2;        // 0..60
            *(float4*)&Bs[row][c4] = *(const float4*)&W[(size_t)(kt + row) * N + n0 + c4];
        }
        __syncthreads();

        #pragma unroll 8
        for (int kk = 0; kk < 32; kk++) {
            float4 a4 = *(const float4*)&As[kk][ty << 2];
            float4 b4 = *(const float4*)&Bs[kk][tx << 2];
            float ar[4] = {a4.x, a4.y, a4.z, a4.w};
            float br[4] = {b4.x, b4.y, b4.z, b4.w};
            #pragma unroll
            for (int i = 0; i < 4; i++)
                #pragma unroll
                for (int j = 0; j < 4; j++)
                    acc[i][j] += ar[i] * br[j];
        }
        __syncthreads();
    }

    #pragma unroll
    for (int i = 0; i < 4; i++) {
        int m = m0 + (ty << 2) + i;
        int n = n0 + (tx << 2);
        float4 o;
        o.x = acc[i][0] + bias[n+0];
        o.y = acc[i][1] + bias[n+1];
        o.z = acc[i][2] + bias[n+2];
        o.w = acc[i][3] + bias[n+3];
        *(float4*)&C[(size_t)m * N + n] = o;
    }
}

// ---------------- Flash attention ----------------
// grid = (S/64, H, B), 256 threads. One CTA handles 64 queries of one head.
// Dynamic smem: Qt[64d][64q] | Kt[64d][64k] | Vs[64k][64d] | Ps[64q][64k]  = 64 KB
__global__ __launch_bounds__(256)
void attn_kernel(const float* __restrict__ qkv, float* __restrict__ av)
{
    extern __shared__ float sm[];
    float* Qt = sm;             // [d][q]
    float* Kt = sm + 4096;      // [d][k]
    float* Vs = sm + 8192;      // [k][d]
    float* Ps = sm + 12288;     // [q][k]

    const int tid = threadIdx.x;
    const int tx  = tid & 15;
    const int ty  = tid >> 4;
    const int qt  = blockIdx.x;
    const int h   = blockIdx.y;
    const int b   = blockIdx.z;
    const int q0  = qt * 64;

    // load Q tile (transposed, pre-scaled by 1/sqrt(HD) = 0.125)
    #pragma unroll
    for (int l = 0; l < 4; l++) {
        int idx = tid + l * 256;          // 0..1023
        int row = idx >> 4;               // query 0..63
        int c4  = (idx & 15) << 2;        // d 0..60
        const float* qp = qkv + (size_t)(b * SS + q0 + row) * DM3 + h * HD + c4;
        float4 v = *(const float4*)qp;
        Qt[(c4+0)*64 + row] = v.x * 0.125f;
        Qt[(c4+1)*64 + row] = v.y * 0.125f;
        Qt[(c4+2)*64 + row] = v.z * 0.125f;
        Qt[(c4+3)*64 + row] = v.w * 0.125f;
    }

    float m_i[4], l_i[4], o[4][4];
    #pragma unroll
    for (int i = 0; i < 4; i++) {
        m_i[i] = -INFINITY; l_i[i] = 0.f;
        #pragma unroll
        for (int j = 0; j < 4; j++) o[i][j] = 0.f;
    }
    __syncthreads();

    for (int t = 0; t < SS / 64; t++) {
        // load K (transposed) and V (natural) tiles
        #pragma unroll
        for (int l = 0; l < 4; l++) {
            int idx = tid + l * 256;
            int row = idx >> 4;
            int c4  = (idx & 15) << 2;
            const float* kp = qkv + (size_t)(b * SS + t * 64 + row) * DM3 + h * HD + DM + c4;
            float4 kv = *(const float4*)kp;
            Kt[(c4+0)*64 + row] = kv.x;
            Kt[(c4+1)*64 + row] = kv.y;
            Kt[(c4+2)*64 + row] = kv.z;
            Kt[(c4+3)*64 + row] = kv.w;
            float4 vv = *(const float4*)(kp + DM);   // v at +2*DM total
            *(float4*)&Vs[row * 64 + c4] = vv;
        }
        __syncthreads();

        // S = Q K^T (scaled)
        float sv[4][4] = {};
        #pragma unroll 8
        for (int d = 0; d < 64; d++) {
            float4 qa = *(const float4*)&Qt[d * 64 + (ty << 2)];
            float4 ka = *(const float4*)&Kt[d * 64 + (tx << 2)];
            float qr[4] = {qa.x, qa.y, qa.z, qa.w};
            float kr[4] = {ka.x, ka.y, ka.z, ka.w};
            #pragma unroll
            for (int i = 0; i < 4; i++)
                #pragma unroll
                for (int j = 0; j < 4; j++)
                    sv[i][j] += qr[i] * kr[j];
        }

        // online softmax (row groups = 16 lanes within a half-warp)
        #pragma unroll
        for (int i = 0; i < 4; i++) {
            float rm = fmaxf(fmaxf(sv[i][0], sv[i][1]), fmaxf(sv[i][2], sv[i][3]));
            #pragma unroll
            for (int off = 8; off >= 1; off >>= 1)
                rm = fmaxf(rm, __shfl_xor_sync(0xffffffffu, rm, off));
            float mn = fmaxf(m_i[i], rm);
            float alpha = __expf(m_i[i] - mn);
            float rs = 0.f;
            #pragma unroll
            for (int j = 0; j < 4; j++) {
                sv[i][j] = __expf(sv[i][j] - mn);
                rs += sv[i][j];
            }
            #pragma unroll
            for (int off = 8; off >= 1; off >>= 1)
                rs += __shfl_xor_sync(0xffffffffu, rs, off);
            l_i[i] = l_i[i] * alpha + rs;
            m_i[i] = mn;
            #pragma unroll
            for (int j = 0; j < 4; j++) o[i][j] *= alpha;
            // store P row-major [q][k] (conflict-free float4 store)
            *(float4*)&Ps[((ty << 2) + i) * 64 + (tx << 2)] =
                make_float4(sv[i][0], sv[i][1], sv[i][2], sv[i][3]);
        }
        __syncthreads();

        // O += P @ V   (thread owns q = ty*4+i, d = tx*4+j)
        #pragma unroll 4
        for (int k0 = 0; k0 < 64; k0 += 4) {
            float pr[4][4], vr[4][4];
            #pragma unroll
            for (int i = 0; i < 4; i++) {
                float4 p4 = *(const float4*)&Ps[((ty << 2) + i) * 64 + k0];
                pr[i][0] = p4.x; pr[i][1] = p4.y; pr[i][2] = p4.z; pr[i][3] = p4.w;
            }
            #pragma unroll
            for (int kk = 0; kk < 4; kk++) {
                float4 v4 = *(const float4*)&Vs[(k0 + kk) * 64 + (tx << 2)];
                vr[kk][0] = v4.x; vr[kk][1] = v4.y; vr[kk][2] = v4.z; vr[kk][3] = v4.w;
            }
            #pragma unroll
            for (int i = 0; i < 4; i++)
                #pragma unroll
                for (int kk = 0; kk < 4; kk++)
                    #pragma unroll
                    for (int j = 0; j < 4; j++)
                        o[i][j] += pr[i][kk] * vr[kk][j];
        }
        __syncthreads();
    }

    // epilogue: O / l  ->  av[b][q][h*64+d]
    #pragma unroll
    for (int i = 0; i < 4; i++) {
        float inv = 1.f / l_i[i];
        float4 ov = make_float4(o[i][0]*inv, o[i][1]*inv, o[i][2]*inv, o[i][3]*inv);
        int q = q0 + (ty << 2) + i;
        *(float4*)&av[(size_t)(b * SS + q) * DM + h * HD + (tx << 2)] = ov;
    }
}

// ---------------- residual + scalar-affine norm ----------------
// x = (RELU ? relu(x1) : x1) + x2;  out = (x-mean)/std * scale + bias  (per 768-row)
__device__ __forceinline__ float block_sum256(float v, float* red)
{
    int lane = threadIdx.x & 31, w = threadIdx.x >> 5;
    #pragma unroll
    for (int m = 16; m > 0; m >>= 1) v += __shfl_xor_sync(0xffffffffu, v, m);
    if (lane == 0) red[w] = v;
    __syncthreads();
    if (w == 0) {
        float t = (lane < 8) ? red[lane] : 0.f;
        #pragma unroll
        for (int m = 4; m > 0; m >>= 1) t += __shfl_xor_sync(0xffffffffu, t, m);
        if (lane == 0) red[0] = t;
    }
    __syncthreads();
    float r = red[0];
    __syncthreads();
    return r;
}

template<bool RELU>
__global__ __launch_bounds__(256)
void norm_kernel(const float* __restrict__ x1, const float* __restrict__ x2,
                 const float* __restrict__ scale, const float* __restrict__ bias,
                 float* __restrict__ out)
{
    __shared__ float red[32];
    const size_t row = blockIdx.x;
    const int tid = threadIdx.x;
    const float* p1 = x1 + row * DM;
    const float* p2 = x2 + row * DM;

    float v[3];
    float s = 0.f;
    #pragma unroll
    for (int l = 0; l < 3; l++) {
        float a = p1[tid + l * 256];
        if (RELU) a = fmaxf(a, 0.f);
        v[l] = a + p2[tid + l * 256];
        s += v[l];
    }
    float mean = block_sum256(s, red) * (1.f / DM);
    float sq = 0.f;
    #pragma unroll
    for (int l = 0; l < 3; l++) { float d = v[l] - mean; sq += d * d; }
    float var = block_sum256(sq, red) * (1.f / DM);
    float inv_std = rsqrtf(var);
    float sc = scale[0], bi = bias[0];
    #pragma unroll
    for (int l = 0; l < 3; l++)
        out[row * DM + tid + l * 256] = (v[l] - mean) * inv_std * sc + bi;
}

// ---------------- launch ----------------
extern "C" void kernel_launch(void* const* d_in, const int* in_sizes, int n_in,
                              void* d_out, int out_size)
{
    const float* base = (const float*)d_in[0];
    const float* Wqkv = (const float*)d_in[1];
    const float* bqkv = (const float*)d_in[2];
    const float* W1   = (const float*)d_in[3];
    const float* b1   = (const float*)d_in[4];
    const float* W2   = (const float*)d_in[5];
    const float* b2   = (const float*)d_in[6];
    const float* n1s  = (const float*)d_in[7];
    const float* n1b  = (const float*)d_in[8];
    const float* n2s  = (const float*)d_in[9];
    const float* n2b  = (const float*)d_in[10];
    float* out = (float*)d_out;

    float *qkv, *av, *t1, *hid;
    cudaGetSymbolAddress((void**)&qkv, g_qkv);
    cudaGetSymbolAddress((void**)&av,  g_av);
    cudaGetSymbolAddress((void**)&t1,  g_t1);
    cudaGetSymbolAddress((void**)&hid, g_hid);

    cudaFuncSetAttribute(attn_kernel, cudaFuncAttributeMaxDynamicSharedMemorySize, 65536);

    // 1) qkv = base @ Wqkv + bqkv
    gemm_bias<DM3, DM><<<dim3(DM3/64, MR/64), 256>>>(base, Wqkv, bqkv, qkv);
    // 2) attention -> av
    attn_kernel<<<dim3(SS/64, NH, BB), 256, 65536>>>(qkv, av);
    // 3) t1 = av @ W1 + b1
    gemm_bias<DM, DM><<<dim3(DM/64, MR/64), 256>>>(av, W1, b1, t1);
    // 4) hid = norm(t1 + base)
    norm_kernel<false><<<MR, 256>>>(t1, base, n1s, n1b, hid);
    // 5) t1 = hid @ W2 + b2
    gemm_bias<DM, DM><<<dim3(DM/64, MR/64), 256>>>(hid, W2, b2, t1);
    // 6) out = norm(relu(t1) + hid)
    norm_kernel<true><<<MR, 256>>>(t1, hid, n2s, n2b, out);
}

// round 2
// speedup vs baseline: 1.0003x; 1.0003x over previous
#include <cuda_runtime.h>
#include <math.h>

#define BB 4
#define SS 2048
#define DM 768
#define NH 12
#define HD 64
#define DM3 2304
#define MR (BB*SS)   // 8192 rows

// ---------------- scratch (device globals; no allocation allowed) ----------------
__device__ float g_qkv[MR*DM3];   // 75.5 MB : [b][s][3*DM]  (q | k | v, head-major inside)
__device__ float g_av [MR*DM];    // 25 MB   : attention output
__device__ float g_t1 [MR*DM];    // 25 MB   : GEMM temporaries
__device__ float g_hid[MR*DM];    // 25 MB   : hidden after norm1

// ---------------- GEMM:  C[M,N] = A[M,K] @ W[K,N] + bias[N] ----------------
// 64x64 tile, BK=32, 256 threads, 4x4 register blocking.
template<int N, int K>
__global__ __launch_bounds__(256)
void gemm_bias(const float* __restrict__ A, const float* __restrict__ W,
               const float* __restrict__ bias, float* __restrict__ C)
{
    __shared__ float As[32][64];   // transposed: As[k][m]
    __shared__ float Bs[32][64];   // Bs[k][n]

    const int tid = threadIdx.x;
    const int tx  = tid & 15;      // n group
    const int ty  = tid >> 4;      // m group
    const int m0  = blockIdx.y * 64;
    const int n0  = blockIdx.x * 64;

    float acc[4][4] = {};

    for (int kt = 0; kt < K; kt += 32) {
        // load A tile 64x32 (transposed into smem)
        #pragma unroll
        for (int l = 0; l < 2; l++) {
            int idx = tid + l * 256;          // 0..511
            int row = idx >> 3;               // 0..63
            int c4  = (idx & 7) << 2;         // 0..28
            float4 a = *(const float4*)&A[(size_t)(m0 + row) * K + kt + c4];
            As[c4+0][row] = a.x; As[c4+1][row] = a.y;
            As[c4+2][row] = a.z; As[c4+3][row] = a.w;
        }
        // load B tile 32x64
        #pragma unroll
        for (int l = 0; l < 2; l++) {
            int idx = tid + l * 256;
            int row = idx >> 4;               // 0..31
            int c4  = (idx & 15) << 2;        // 0..60
            *(float4*)&Bs[row][c4] = *(const float4*)&W[(size_t)(kt + row) * N + n0 + c4];
        }
        __syncthreads();

        #pragma unroll 8
        for (int kk = 0; kk < 32; kk++) {
            float4 a4 = *(const float4*)&As[kk][ty << 2];
            float4 b4 = *(const float4*)&Bs[kk][tx << 2];
            float ar[4] = {a4.x, a4.y, a4.z, a4.w};
            float br[4] = {b4.x, b4.y, b4.z, b4.w};
            #pragma unroll
            for (int i = 0; i < 4; i++)
                #pragma unroll
                for (int j = 0; j < 4; j++)
                    acc[i][j] += ar[i] * br[j];
        }
        __syncthreads();
    }

    #pragma unroll
    for (int i = 0; i < 4; i++) {
        int m = m0 + (ty << 2) + i;
        int n = n0 + (tx << 2);
        float4 o;
        o.x = acc[i][0] + bias[n+0];
        o.y = acc[i][1] + bias[n+1];
        o.z = acc[i][2] + bias[n+2];
        o.w = acc[i][3] + bias[n+3];
        *(float4*)&C[(size_t)m * N + n] = o;
    }
}

// ---------------- Flash attention ----------------
// grid = (S/64, H, B), 256 threads. One CTA handles 64 queries of one head.
// Dynamic smem: Qt[64d][64q] | Kt[64d][64k] | Vs[64k][64d] | Ps[64q][64k]  = 64 KB
__global__ __launch_bounds__(256)
void attn_kernel(const float* __restrict__ qkv, float* __restrict__ av)
{
    extern __shared__ float sm[];
    float* Qt = sm;             // [d][q]
    float* Kt = sm + 4096;      // [d][k]
    float* Vs = sm + 8192;      // [k][d]
    float* Ps = sm + 12288;     // [q][k]

    const int tid = threadIdx.x;
    const int tx  = tid & 15;
    const int ty  = tid >> 4;
    const int qt  = blockIdx.x;
    const int h   = blockIdx.y;
    const int b   = blockIdx.z;
    const int q0  = qt * 64;

    // load Q tile (transposed, pre-scaled by 1/sqrt(HD) = 0.125)
    #pragma unroll
    for (int l = 0; l < 4; l++) {
        int idx = tid + l * 256;          // 0..1023
        int row = idx >> 4;               // query 0..63
        int c4  = (idx & 15) << 2;        // d 0..60
        const float* qp = qkv + (size_t)(b * SS + q0 + row) * DM3 + h * HD + c4;
        float4 v = *(const float4*)qp;
        Qt[(c4+0)*64 + row] = v.x * 0.125f;
        Qt[(c4+1)*64 + row] = v.y * 0.125f;
        Qt[(c4+2)*64 + row] = v.z * 0.125f;
        Qt[(c4+3)*64 + row] = v.w * 0.125f;
    }

    float m_i[4], l_i[4], o[4][4];
    #pragma unroll
    for (int i = 0; i < 4; i++) {
        m_i[i] = -INFINITY; l_i[i] = 0.f;
        #pragma unroll
        for (int j = 0; j < 4; j++) o[i][j] = 0.f;
    }
    __syncthreads();

    for (int t = 0; t < SS / 64; t++) {
        // load K (transposed) and V (natural) tiles
        #pragma unroll
        for (int l = 0; l < 4; l++) {
            int idx = tid + l * 256;
            int row = idx >> 4;
            int c4  = (idx & 15) << 2;
            const float* kp = qkv + (size_t)(b * SS + t * 64 + row) * DM3 + h * HD + DM + c4;
            float4 kv = *(const float4*)kp;
            Kt[(c4+0)*64 + row] = kv.x;
            Kt[(c4+1)*64 + row] = kv.y;
            Kt[(c4+2)*64 + row] = kv.z;
            Kt[(c4+3)*64 + row] = kv.w;
            float4 vv = *(const float4*)(kp + DM);   // v at +2*DM total
            *(float4*)&Vs[row * 64 + c4] = vv;
        }
        __syncthreads();

        // S = Q K^T (scaled)
        float sv[4][4] = {};
        #pragma unroll 8
        for (int d = 0; d < 64; d++) {
            float4 qa = *(const float4*)&Qt[d * 64 + (ty << 2)];
            float4 ka = *(const float4*)&Kt[d * 64 + (tx << 2)];
            float qr[4] = {qa.x, qa.y, qa.z, qa.w};
            float kr[4] = {ka.x, ka.y, ka.z, ka.w};
            #pragma unroll
            for (int i = 0; i < 4; i++)
                #pragma unroll
                for (int j = 0; j < 4; j++)
                    sv[i][j] += qr[i] * kr[j];
        }

        // online softmax (row groups = 16 lanes within a half-warp)
        #pragma unroll
        for (int i = 0; i < 4; i++) {
            float rm = fmaxf(fmaxf(sv[i][0], sv[i][1]), fmaxf(sv[i][2], sv[i][3]));
            #pragma unroll
            for (int off = 8; off >= 1; off >>= 1)
                rm = fmaxf(rm, __shfl_xor_sync(0xffffffffu, rm, off));
            float mn = fmaxf(m_i[i], rm);
            float alpha = __expf(m_i[i] - mn);
            float rs = 0.f;
            #pragma unroll
            for (int j = 0; j < 4; j++) {
                sv[i][j] = __expf(sv[i][j] - mn);
                rs += sv[i][j];
            }
            #pragma unroll
            for (int off = 8; off >= 1; off >>= 1)
                rs += __shfl_xor_sync(0xffffffffu, rs, off);
            l_i[i] = l_i[i] * alpha + rs;
            m_i[i] = mn;
            #pragma unroll
            for (int j = 0; j < 4; j++) o[i][j] *= alpha;
            // store P row-major [q][k] (conflict-free float4 store)
            *(float4*)&Ps[((ty << 2) + i) * 64 + (tx << 2)] =
                make_float4(sv[i][0], sv[i][1], sv[i][2], sv[i][3]);
        }
        __syncthreads();

        // O += P @ V   (thread owns q = ty*4+i, d = tx*4+j)
        #pragma unroll 4
        for (int k0 = 0; k0 < 64; k0 += 4) {
            float pr[4][4], vr[4][4];
            #pragma unroll
            for (int i = 0; i < 4; i++) {
                float4 p4 = *(const float4*)&Ps[((ty << 2) + i) * 64 + k0];
                pr[i][0] = p4.x; pr[i][1] = p4.y; pr[i][2] = p4.z; pr[i][3] = p4.w;
            }
            #pragma unroll
            for (int kk = 0; kk < 4; kk++) {
                float4 v4 = *(const float4*)&Vs[(k0 + kk) * 64 + (tx << 2)];
                vr[kk][0] = v4.x; vr[kk][1] = v4.y; vr[kk][2] = v4.z; vr[kk][3] = v4.w;
            }
            #pragma unroll
            for (int i = 0; i < 4; i++)
                #pragma unroll
                for (int kk = 0; kk < 4; kk++)
                    #pragma unroll
                    for (int j = 0; j < 4; j++)
                        o[i][j] += pr[i][kk] * vr[kk][j];
        }
        __syncthreads();
    }

    // epilogue: O / l  ->  av[b][q][h*64+d]
    #pragma unroll
    for (int i = 0; i < 4; i++) {
        float inv = 1.f / l_i[i];
        float4 ov = make_float4(o[i][0]*inv, o[i][1]*inv, o[i][2]*inv, o[i][3]*inv);
        int q = q0 + (ty << 2) + i;
        *(float4*)&av[(size_t)(b * SS + q) * DM + h * HD + (tx << 2)] = ov;
    }
}

// ---------------- residual + scalar-affine norm ----------------
// x = (RELU ? relu(x1) : x1) + x2;  out = (x-mean)/std * scale + bias  (per 768-row)
__device__ __forceinline__ float block_sum256(float v, float* red)
{
    int lane = threadIdx.x & 31, w = threadIdx.x >> 5;
    #pragma unroll
    for (int m = 16; m > 0; m >>= 1) v += __shfl_xor_sync(0xffffffffu, v, m);
    if (lane == 0) red[w] = v;
    __syncthreads();
    if (w == 0) {
        float t = (lane < 8) ? red[lane] : 0.f;
        #pragma unroll
        for (int m = 4; m > 0; m >>= 1) t += __shfl_xor_sync(0xffffffffu, t, m);
        if (lane == 0) red[0] = t;
    }
    __syncthreads();
    float r = red[0];
    __syncthreads();
    return r;
}

template<bool RELU>
__global__ __launch_bounds__(256)
void norm_kernel(const float* __restrict__ x1, const float* __restrict__ x2,
                 const float* __restrict__ scale, const float* __restrict__ bias,
                 float* __restrict__ out)
{
    __shared__ float red[32];
    const size_t row = blockIdx.x;
    const int tid = threadIdx.x;
    const float* p1 = x1 + row * DM;
    const float* p2 = x2 + row * DM;

    float v[3];
    float s = 0.f;
    #pragma unroll
    for (int l = 0; l < 3; l++) {
        float a = p1[tid + l * 256];
        if (RELU) a = fmaxf(a, 0.f);
        v[l] = a + p2[tid + l * 256];
        s += v[l];
    }
    float mean = block_sum256(s, red) * (1.f / DM);
    float sq = 0.f;
    #pragma unroll
    for (int l = 0; l < 3; l++) { float d = v[l] - mean; sq += d * d; }
    float var = block_sum256(sq, red) * (1.f / DM);
    float inv_std = rsqrtf(var);
    float sc = scale[0], bi = bias[0];
    #pragma unroll
    for (int l = 0; l < 3; l++)
        out[row * DM + tid + l * 256] = (v[l] - mean) * inv_std * sc + bi;
}

// ---------------- launch ----------------
extern "C" void kernel_launch(void* const* d_in, const int* in_sizes, int n_in,
                              void* d_out, int out_size)
{
    const float* base = (const float*)d_in[0];
    const float* Wqkv = (const float*)d_in[1];
    const float* bqkv = (const float*)d_in[2];
    const float* W1   = (const float*)d_in[3];
    const float* b1   = (const float*)d_in[4];
    const float* W2   = (const float*)d_in[5];
    const float* b2   = (const float*)d_in[6];
    const float* n1s  = (const float*)d_in[7];
    const float* n1b  = (const float*)d_in[8];
    const float* n2s  = (const float*)d_in[9];
    const float* n2b  = (const float*)d_in[10];
    float* out = (float*)d_out;

    float *qkv, *av, *t1, *hid;
    cudaGetSymbolAddress((void**)&qkv, g_qkv);
    cudaGetSymbolAddress((void**)&av,  g_av);
    cudaGetSymbolAddress((void**)&t1,  g_t1);
    cudaGetSymbolAddress((void**)&hid, g_hid);

    cudaFuncSetAttribute(attn_kernel, cudaFuncAttributeMaxDynamicSharedMemorySize, 65536);

    // 1) qkv = base @ Wqkv + bqkv
    gemm_bias<DM3, DM><<<dim3(DM3/64, MR/64), 256>>>(base, Wqkv, bqkv, qkv);
    // 2) attention -> av
    attn_kernel<<<dim3(SS/64, NH, BB), 256, 65536>>>(qkv, av);
    // 3) t1 = av @ W1 + b1
    gemm_bias<DM, DM><<<dim3(DM/64, MR/64), 256>>>(av, W1, b1, t1);
    // 4) hid = norm(t1 + base)
    norm_kernel<false><<<MR, 256>>>(t1, base, n1s, n1b, hid);
    // 5) t1 = hid @ W2 + b2
    gemm_bias<DM, DM><<<dim3(DM/64, MR/64), 256>>>(hid, W2, b2, t1);
    // 6) out = norm(relu(t1) + hid)
    norm_kernel<true><<<MR, 256>>>(t1, hid, n2s, n2b, out);
}

// round 4
// speedup vs baseline: 8.3161x; 8.3132x over previous
#include <cuda_runtime.h>
#include <cuda_fp16.h>
#include <math.h>
#include <stdint.h>

#define BB 4
#define SS 2048
#define DM 768
#define NH 12
#define HD 64
#define DM3 2304
#define MR (BB*SS)

// ---------------- scratch ----------------
__device__ float  g_qkv[(size_t)MR*DM3];
__device__ float  g_t1 [(size_t)MR*DM];
__device__ float  g_hid[(size_t)MR*DM];
__device__ __half g_bh [(size_t)MR*DM];
__device__ __half g_qh [(size_t)MR*DM];   // [b*NH+h][s][64], pre-scaled 0.125
__device__ __half g_kh [(size_t)MR*DM];   // [b*NH+h][s][64]
__device__ __half g_vt [(size_t)MR*DM];   // [b*NH+h][64][2048]  (V^T)
__device__ __half g_av [(size_t)MR*DM];   // [row][768]
__device__ __half g_hh [(size_t)MR*DM];
__device__ __half g_wqT[(size_t)DM3*DM];  // [2304][768]
__device__ __half g_w1T[(size_t)DM*DM];
__device__ __half g_w2T[(size_t)DM*DM];

// ---------------- helpers ----------------
__device__ __forceinline__ uint32_t smem_u32(const void* p){
    uint32_t a;
    asm("{ .reg .u64 t; cvta.to.shared.u64 t, %1; cvt.u32.u64 %0, t; }" : "=r"(a) : "l"(p));
    return a;
}
#define CPA(dst, src) asm volatile("cp.async.cg.shared.global [%0], [%1], 16;" :: "r"((uint32_t)(dst)), "l"(src) : "memory")
#define CPA_COMMIT() asm volatile("cp.async.commit_group;" ::: "memory")
#define CPA_WAIT0() asm volatile("cp.async.wait_group 0;" ::: "memory")
#define CPA_WAIT1() asm volatile("cp.async.wait_group 1;" ::: "memory")

__device__ __forceinline__ uint32_t swz(uint32_t o){ return o ^ ((o >> 3) & 0x70); } // 128B-row SW128

__device__ __forceinline__ void ldsm4(uint32_t &r0, uint32_t &r1, uint32_t &r2, uint32_t &r3, uint32_t a){
    asm volatile("ldmatrix.sync.aligned.m8n8.x4.shared.b16 {%0,%1,%2,%3}, [%4];"
                 : "=r"(r0), "=r"(r1), "=r"(r2), "=r"(r3) : "r"(a));
}
__device__ __forceinline__ void mma16816(float* c, uint32_t a0, uint32_t a1, uint32_t a2, uint32_t a3,
                                         uint32_t b0, uint32_t b1){
    asm volatile("mma.sync.aligned.m16n8k16.row.col.f32.f16.f16.f32 "
                 "{%0,%1,%2,%3}, {%4,%5,%6,%7}, {%8,%9}, {%0,%1,%2,%3};"
                 : "+f"(c[0]), "+f"(c[1]), "+f"(c[2]), "+f"(c[3])
                 : "r"(a0), "r"(a1), "r"(a2), "r"(a3), "r"(b0), "r"(b1));
}
__device__ __forceinline__ uint32_t pack2(float a, float b){
    __half2 h = __floats2half2_rn(a, b);
    return *(uint32_t*)&h;
}

// ---------------- conversions ----------------
__global__ __launch_bounds__(256) void conv_base(const float* __restrict__ in, __half* __restrict__ out, int n){
    for (int i = blockIdx.x*256 + threadIdx.x; i < n; i += gridDim.x*256)
        out[i] = __float2half_rn(in[i]);
}

// W [K][N] fp32 -> T [N][K] f16
__global__ __launch_bounds__(256)
void transp_conv(const float* __restrict__ W, __half* __restrict__ T, int K, int N){
    __shared__ float s[32][33];
    int j = threadIdx.x & 31, i0 = threadIdx.x >> 5;
    int n0 = blockIdx.x*32, k0 = blockIdx.y*32;
    #pragma unroll
    for (int l = 0; l < 4; l++){ int i = i0 + l*8; s[i][j] = W[(size_t)(k0+i)*N + n0 + j]; }
    __syncthreads();
    #pragma unroll
    for (int l = 0; l < 4; l++){
        int i = i0 + l*8;
        T[(size_t)(n0+i)*K + k0 + j] = __float2half_rn(s[j][i]);
    }
}

// qkv fp32 -> q(scaled),k f16 [bh][s][64] ; v^T f16 [bh][64][2048]
__global__ __launch_bounds__(128)
void conv_qkv(const float* __restrict__ qkv, __half* __restrict__ q, __half* __restrict__ k, __half* __restrict__ vt){
    __shared__ float sv[128][65];
    int st = blockIdx.x, h = blockIdx.y, b = blockIdx.z;
    int bh = b*NH + h;
    int s0 = st*128;
    for (int idx = threadIdx.x; idx < 128*64; idx += 128){
        int s = idx >> 6, d = idx & 63;
        const float* row = qkv + (size_t)(b*SS + s0 + s)*DM3 + h*64 + d;
        q[((size_t)bh*SS + s0 + s)*64 + d] = __float2half_rn(row[0] * 0.125f);
        k[((size_t)bh*SS + s0 + s)*64 + d] = __float2half_rn(row[DM]);
        sv[s][d] = row[2*DM];
    }
    __syncthreads();
    for (int idx = threadIdx.x; idx < 64*128; idx += 128){
        int d = idx >> 7, s = idx & 127;
        vt[((size_t)bh*64 + d)*SS + s0 + s] = __float2half_rn(sv[s][d]);
    }
}

// ---------------- GEMM: C[M,N] = A[M,K]@B^T + bias (A[M][K], B[N][K] f16, C fp32) ----------------
template<int N, int K>
__global__ __launch_bounds__(256, 2)
void gemm_h(const __half* __restrict__ A, const __half* __restrict__ B,
            const float* __restrict__ bias, float* __restrict__ C)
{
    extern __shared__ char sm[];
    const uint32_t sb = smem_u32(sm);
    const int tid = threadIdx.x, lane = tid & 31, wid = tid >> 5;
    const int wm = (wid & 1)*64, wn = (wid >> 1)*32;
    const int m0 = blockIdx.y*128, n0 = blockIdx.x*128;
    const int NC = K/64;

    float acc[4][4][4] = {};

    auto load = [&](int c, int s){
        uint32_t sa = sb + s*32768, sbm = sa + 16384;
        int k0 = c*64;
        #pragma unroll
        for (int l = 0; l < 4; l++){
            int idx = tid + l*256;
            int r = idx >> 3, c16 = idx & 7;
            uint32_t o = swz((uint32_t)(r*128 + c16*16));
            CPA(sa  + o, (const char*)(A + (size_t)(m0+r)*K + k0 + c16*8));
            CPA(sbm + o, (const char*)(B + (size_t)(n0+r)*K + k0 + c16*8));
        }
        CPA_COMMIT();
    };

    load(0, 0);
    for (int c = 0; c < NC; c++){
        int s = c & 1;
        if (c+1 < NC) load(c+1, 1-s);
        if (c+1 < NC) CPA_WAIT1(); else CPA_WAIT0();
        __syncthreads();
        uint32_t sa = sb + s*32768, sbm = sa + 16384;
        #pragma unroll
        for (int ks = 0; ks < 4; ks++){
            uint32_t a[4][4];
            #pragma unroll
            for (int mt = 0; mt < 4; mt++)
                ldsm4(a[mt][0], a[mt][1], a[mt][2], a[mt][3],
                      sa + swz((uint32_t)((wm + mt*16 + (lane & 15))*128 + (ks*16 + ((lane >> 4) << 3))*2)));
            #pragma unroll
            for (int np = 0; np < 2; np++){
                uint32_t b0, b1, b2, b3;
                int n  = wn + np*16 + ((lane >> 4) << 3) + (lane & 7);
                int kh = ks*16 + ((lane >> 3) & 1)*8;
                ldsm4(b0, b1, b2, b3, sbm + swz((uint32_t)(n*128 + kh*2)));
                #pragma unroll
                for (int mt = 0; mt < 4; mt++){
                    mma16816(acc[mt][np*2],   a[mt][0], a[mt][1], a[mt][2], a[mt][3], b0, b1);
                    mma16816(acc[mt][np*2+1], a[mt][0], a[mt][1], a[mt][2], a[mt][3], b2, b3);
                }
            }
        }
        __syncthreads();
    }

    #pragma unroll
    for (int mt = 0; mt < 4; mt++){
        int row = m0 + wm + mt*16 + (lane >> 2);
        #pragma unroll
        for (int nt = 0; nt < 4; nt++){
            int col = n0 + wn + nt*8 + 2*(lane & 3);
            float2 bi = *(const float2*)&bias[col];
            float2 o0 = { acc[mt][nt][0] + bi.x, acc[mt][nt][1] + bi.y };
            float2 o1 = { acc[mt][nt][2] + bi.x, acc[mt][nt][3] + bi.y };
            *(float2*)&C[(size_t)row*N + col]     = o0;
            *(float2*)&C[(size_t)(row+8)*N + col] = o1;
        }
    }
}

// ---------------- attention: CTA = (128-query tile, bh); 8 warps x 16 q-rows ----------------
__global__ __launch_bounds__(256, 2)
void attn_h(const __half* __restrict__ Q, const __half* __restrict__ Kh,
            const __half* __restrict__ Vt, __half* __restrict__ av)
{
    extern __shared__ char sm[];
    const uint32_t sb = smem_u32(sm);
    const uint32_t SQ = sb;            // 16KB
    const uint32_t SK = sb + 16384;    // 2 x 16KB
    const uint32_t SV = sb + 49152;    // 2 x 16KB (each stage: two 8KB 64-key halves)
    const int tid = threadIdx.x, lane = tid & 31, wid = tid >> 5;
    const int q0 = blockIdx.x*128, bh = blockIdx.y;
    const __half* Qp = Q  + (size_t)bh*SS*64 + (size_t)q0*64;
    const __half* Kp = Kh + (size_t)bh*SS*64;
    const __half* Vp = Vt + (size_t)bh*64*SS;

    // preload Q + K0 + V0
    #pragma unroll
    for (int l = 0; l < 4; l++){
        int idx = tid + l*256; int r = idx >> 3, c = idx & 7;
        uint32_t o = swz((uint32_t)(r*128 + c*16));
        CPA(SQ + o, (const char*)(Qp + r*64 + c*8));
        CPA(SK + o, (const char*)(Kp + r*64 + c*8));
    }
    #pragma unroll
    for (int l = 0; l < 4; l++){
        int idx = tid + l*256; int d = idx >> 4, c = idx & 15;
        CPA(SV + (c >> 3)*8192 + swz((uint32_t)(d*128 + (c & 7)*16)), (const char*)(Vp + (size_t)d*SS + c*8));
    }
    CPA_COMMIT();

    float o[8][4] = {};
    float rs0 = 0.f, rs1 = 0.f;
    uint32_t qf[4][4];
    bool qloaded = false;

    for (int t = 0; t < 16; t++){
        int s = t & 1;
        if (t+1 < 16){
            const __half* Kn = Kp + (size_t)(t+1)*128*64;
            #pragma unroll
            for (int l = 0; l < 4; l++){
                int idx = tid + l*256; int r = idx >> 3, c = idx & 7;
                CPA(SK + (1-s)*16384 + swz((uint32_t)(r*128 + c*16)), (const char*)(Kn + r*64 + c*8));
            }
            #pragma unroll
            for (int l = 0; l < 4; l++){
                int idx = tid + l*256; int d = idx >> 4, c = idx & 15;
                CPA(SV + (1-s)*16384 + (c >> 3)*8192 + swz((uint32_t)(d*128 + (c & 7)*16)),
                    (const char*)(Vp + (size_t)d*SS + (t+1)*128 + c*8));
            }
            CPA_COMMIT();
            CPA_WAIT1();
        } else CPA_WAIT0();
        __syncthreads();

        if (!qloaded){
            #pragma unroll
            for (int ks = 0; ks < 4; ks++)
                ldsm4(qf[ks][0], qf[ks][1], qf[ks][2], qf[ks][3],
                      SQ + swz((uint32_t)((wid*16 + (lane & 15))*128 + (ks*16 + ((lane >> 4) << 3))*2)));
            qloaded = true;
        }

        uint32_t sk = SK + s*16384, sv = SV + s*16384;
        #pragma unroll
        for (int np = 0; np < 8; np++){           // 16-key chunks
            float sacc[2][4] = {};
            #pragma unroll
            for (int ks = 0; ks < 4; ks++){
                uint32_t b0, b1, b2, b3;
                int n  = np*16 + ((lane >> 4) << 3) + (lane & 7);
                int kh = ks*16 + ((lane >> 3) & 1)*8;
                ldsm4(b0, b1, b2, b3, sk + swz((uint32_t)(n*128 + kh*2)));
                mma16816(sacc[0], qf[ks][0], qf[ks][1], qf[ks][2], qf[ks][3], b0, b1);
                mma16816(sacc[1], qf[ks][0], qf[ks][1], qf[ks][2], qf[ks][3], b2, b3);
            }
            float e00 = __expf(sacc[0][0]), e01 = __expf(sacc[0][1]);
            float e02 = __expf(sacc[0][2]), e03 = __expf(sacc[0][3]);
            float e10 = __expf(sacc[1][0]), e11 = __expf(sacc[1][1]);
            float e12 = __expf(sacc[1][2]), e13 = __expf(sacc[1][3]);
            rs0 += e00 + e01 + e10 + e11;
            rs1 += e02 + e03 + e12 + e13;
            uint32_t p0 = pack2(e00, e01), p1 = pack2(e02, e03);
            uint32_t p2 = pack2(e10, e11), p3 = pack2(e12, e13);
            #pragma unroll
            for (int dp = 0; dp < 4; dp++){
                uint32_t b0, b1, b2, b3;
                int d   = dp*16 + ((lane >> 4) << 3) + (lane & 7);
                int key = np*16 + ((lane >> 3) & 1)*8;
                ldsm4(b0, b1, b2, b3, sv + (key >> 6)*8192 + swz((uint32_t)(d*128 + (key & 63)*2)));
                mma16816(o[dp*2],   p0, p1, p2, p3, b0, b1);
                mma16816(o[dp*2+1], p0, p1, p2, p3, b2, b3);
            }
        }
        __syncthreads();
    }

    rs0 += __shfl_xor_sync(~0u, rs0, 1); rs0 += __shfl_xor_sync(~0u, rs0, 2);
    rs1 += __shfl_xor_sync(~0u, rs1, 1); rs1 += __shfl_xor_sync(~0u, rs1, 2);
    float i0 = 1.f/rs0, i1 = 1.f/rs1;
    int b = bh / NH, h = bh % NH;
    int qrow = q0 + wid*16 + (lane >> 2);
    #pragma unroll
    for (int dt = 0; dt < 8; dt++){
        int col = h*64 + dt*8 + 2*(lane & 3);
        *(uint32_t*)&av[(size_t)(b*SS + qrow)*DM + col]     = pack2(o[dt][0]*i0, o[dt][1]*i0);
        *(uint32_t*)&av[(size_t)(b*SS + qrow + 8)*DM + col] = pack2(o[dt][2]*i1, o[dt][3]*i1);
    }
}

// ---------------- residual + scalar-affine norm ----------------
__device__ __forceinline__ float block_sum256(float v, float* red){
    int lane = threadIdx.x & 31, w = threadIdx.x >> 5;
    #pragma unroll
    for (int m = 16; m > 0; m >>= 1) v += __shfl_xor_sync(0xffffffffu, v, m);
    if (lane == 0) red[w] = v;
    __syncthreads();
    if (w == 0){
        float t = (lane < 8) ? red[lane] : 0.f;
        #pragma unroll
        for (int m = 4; m > 0; m >>= 1) t += __shfl_xor_sync(0xffffffffu, t, m);
        if (lane == 0) red[0] = t;
    }
    __syncthreads();
    float r = red[0];
    __syncthreads();
    return r;
}

template<bool RELU, bool EMIT>
__global__ __launch_bounds__(256)
void norm_kernel(const float* __restrict__ x1, const float* __restrict__ x2,
                 const float* __restrict__ scale, const float* __restrict__ bias,
                 float* __restrict__ out, __half* __restrict__ oh)
{
    __shared__ float red[32];
    const size_t row = blockIdx.x;
    const int tid = threadIdx.x;
    const float* p1 = x1 + row*DM;
    const float* p2 = x2 + row*DM;
    float v[3], s = 0.f;
    #pragma unroll
    for (int l = 0; l < 3; l++){
        float a = p1[tid + l*256];
        if (RELU) a = fmaxf(a, 0.f);
        v[l] = a + p2[tid + l*256];
        s += v[l];
    }
    float mean = block_sum256(s, red) * (1.f/DM);
    float sq = 0.f;
    #pragma unroll
    for (int l = 0; l < 3; l++){ float d = v[l] - mean; sq += d*d; }
    float inv_std = rsqrtf(block_sum256(sq, red) * (1.f/DM));
    float sc = scale[0], bi = bias[0];
    #pragma unroll
    for (int l = 0; l < 3; l++){
        float o = (v[l] - mean) * inv_std * sc + bi;
        size_t a = row*DM + tid + l*256;
        out[a] = o;
        if (EMIT) oh[a] = __float2half_rn(o);
    }
}

// ---------------- launch ----------------
extern "C" void kernel_launch(void* const* d_in, const int* in_sizes, int n_in,
                              void* d_out, int out_size)
{
    const float* base = (const float*)d_in[0];
    const float* Wqkv = (const float*)d_in[1];
    const float* bqkv = (const float*)d_in[2];
    const float* W1   = (const float*)d_in[3];
    const float* b1   = (const float*)d_in[4];
    const float* W2   = (const float*)d_in[5];
    const float* b2   = (const float*)d_in[6];
    const float* n1s  = (const float*)d_in[7];
    const float* n1b  = (const float*)d_in[8];
    const float* n2s  = (const float*)d_in[9];
    const float* n2b  = (const float*)d_in[10];
    float* out = (float*)d_out;

    float *qkv, *t1, *hid;
    __half *bh, *qh, *kh, *vt, *av, *hh, *wqT, *w1T, *w2T;
    cudaGetSymbolAddress((void**)&qkv, g_qkv);
    cudaGetSymbolAddress((void**)&t1,  g_t1);
    cudaGetSymbolAddress((void**)&hid, g_hid);
    cudaGetSymbolAddress((void**)&bh,  g_bh);
    cudaGetSymbolAddress((void**)&qh,  g_qh);
    cudaGetSymbolAddress((void**)&kh,  g_kh);
    cudaGetSymbolAddress((void**)&vt,  g_vt);
    cudaGetSymbolAddress((void**)&av,  g_av);
    cudaGetSymbolAddress((void**)&hh,  g_hh);
    cudaGetSymbolAddress((void**)&wqT, g_wqT);
    cudaGetSymbolAddress((void**)&w1T, g_w1T);
    cudaGetSymbolAddress((void**)&w2T, g_w2T);

    cudaFuncSetAttribute(gemm_h<DM3,DM>, cudaFuncAttributeMaxDynamicSharedMemorySize, 65536);
    cudaFuncSetAttribute(gemm_h<DM,DM>,  cudaFuncAttributeMaxDynamicSharedMemorySize, 65536);
    cudaFuncSetAttribute(attn_h,         cudaFuncAttributeMaxDynamicSharedMemorySize, 81920);

    conv_base<<<2048, 256>>>(base, bh, MR*DM);
    transp_conv<<<dim3(DM3/32, DM/32), 256>>>(Wqkv, wqT, DM, DM3);
    transp_conv<<<dim3(DM/32,  DM/32), 256>>>(W1,   w1T, DM, DM);
    transp_conv<<<dim3(DM/32,  DM/32), 256>>>(W2,   w2T, DM, DM);

    gemm_h<DM3,DM><<<dim3(DM3/128, MR/128), 256, 65536>>>(bh, wqT, bqkv, qkv);
    conv_qkv<<<dim3(SS/128, NH, BB), 128>>>(qkv, qh, kh, vt);
    attn_h<<<dim3(SS/128, BB*NH), 256, 81920>>>(qh, kh, vt, av);
    gemm_h<DM,DM><<<dim3(DM/128, MR/128), 256, 65536>>>(av, w1T, b1, t1);
    norm_kernel<false, true><<<MR, 256>>>(t1, base, n1s, n1b, hid, hh);
    gemm_h<DM,DM><<<dim3(DM/128, MR/128), 256, 65536>>>(hh, w2T, b2, t1);
    norm_kernel<true, false><<<MR, 256>>>(t1, hid, n2s, n2b, out, nullptr);
}

// round 5
// speedup vs baseline: 8.9164x; 1.0722x over previous
#include <cuda_runtime.h>
#include <cuda_fp16.h>
#include <math.h>
#include <stdint.h>

#define BB 4
#define SS 2048
#define DM 768
#define NH 12
#define HD 64
#define DM3 2304
#define MR (BB*SS)

// ---------------- scratch ----------------
__device__ float  g_t1 [(size_t)MR*DM];
__device__ float  g_hid[(size_t)MR*DM];
__device__ __half g_bh [(size_t)MR*DM];
__device__ __half g_qh [(size_t)MR*DM];   // [b*NH+h][s][64], pre-scaled 0.125
__device__ __half g_kh [(size_t)MR*DM];   // [b*NH+h][s][64]
__device__ __half g_vt [(size_t)MR*DM];   // [b*NH+h][64][2048]  (V^T)
__device__ __half g_av [(size_t)MR*DM];   // [row][768]
__device__ __half g_hh [(size_t)MR*DM];
__device__ __half g_wqT[(size_t)DM3*DM];  // [2304][768]
__device__ __half g_w1T[(size_t)DM*DM];
__device__ __half g_w2T[(size_t)DM*DM];

// ---------------- helpers ----------------
__device__ __forceinline__ uint32_t smem_u32(const void* p){
    uint32_t a;
    asm("{ .reg .u64 t; cvta.to.shared.u64 t, %1; cvt.u32.u64 %0, t; }" : "=r"(a) : "l"(p));
    return a;
}
#define CPA(dst, src) asm volatile("cp.async.cg.shared.global [%0], [%1], 16;" :: "r"((uint32_t)(dst)), "l"(src) : "memory")
#define CPA_COMMIT() asm volatile("cp.async.commit_group;" ::: "memory")
#define CPA_WAIT0() asm volatile("cp.async.wait_group 0;" ::: "memory")
#define CPA_WAIT1() asm volatile("cp.async.wait_group 1;" ::: "memory")

__device__ __forceinline__ uint32_t swz(uint32_t o){ return o ^ ((o >> 3) & 0x70); } // 128B-row SW128

__device__ __forceinline__ void ldsm4(uint32_t &r0, uint32_t &r1, uint32_t &r2, uint32_t &r3, uint32_t a){
    asm volatile("ldmatrix.sync.aligned.m8n8.x4.shared.b16 {%0,%1,%2,%3}, [%4];"
                 : "=r"(r0), "=r"(r1), "=r"(r2), "=r"(r3) : "r"(a));
}
__device__ __forceinline__ void mma16816(float* c, uint32_t a0, uint32_t a1, uint32_t a2, uint32_t a3,
                                         uint32_t b0, uint32_t b1){
    asm volatile("mma.sync.aligned.m16n8k16.row.col.f32.f16.f16.f32 "
                 "{%0,%1,%2,%3}, {%4,%5,%6,%7}, {%8,%9}, {%0,%1,%2,%3};"
                 : "+f"(c[0]), "+f"(c[1]), "+f"(c[2]), "+f"(c[3])
                 : "r"(a0), "r"(a1), "r"(a2), "r"(a3), "r"(b0), "r"(b1));
}
__device__ __forceinline__ uint32_t pack2(float a, float b){
    __half2 h = __floats2half2_rn(a, b);
    return *(uint32_t*)&h;
}

// ---------------- conversions ----------------
__global__ __launch_bounds__(256) void conv_base(const float* __restrict__ in, __half* __restrict__ out, int n){
    for (int i = blockIdx.x*256 + threadIdx.x; i < n; i += gridDim.x*256)
        out[i] = __float2half_rn(in[i]);
}

// W [K][N] fp32 -> T [N][K] f16
__global__ __launch_bounds__(256)
void transp_conv(const float* __restrict__ W, __half* __restrict__ T, int K, int N){
    __shared__ float s[32][33];
    int j = threadIdx.x & 31, i0 = threadIdx.x >> 5;
    int n0 = blockIdx.x*32, k0 = blockIdx.y*32;
    #pragma unroll
    for (int l = 0; l < 4; l++){ int i = i0 + l*8; s[i][j] = W[(size_t)(k0+i)*N + n0 + j]; }
    __syncthreads();
    #pragma unroll
    for (int l = 0; l < 4; l++){
        int i = i0 + l*8;
        T[(size_t)(n0+i)*K + k0 + j] = __float2half_rn(s[j][i]);
    }
}

// ---------------- GEMM: A[M][K]@B[N][K]^T + bias ----------------
// MODE 0: C fp32 [M][N].  MODE 1: fused QKV epilogue -> qh/kh ([bh][s][64], q scaled) and vt ([bh][64][2048]).
template<int N, int K, int MODE>
__global__ __launch_bounds__(256, 2)
void gemm_h(const __half* __restrict__ A, const __half* __restrict__ B,
            const float* __restrict__ bias, float* __restrict__ C,
            __half* __restrict__ qh, __half* __restrict__ kh, __half* __restrict__ vt)
{
    extern __shared__ char sm[];
    const uint32_t sb = smem_u32(sm);
    const int tid = threadIdx.x, lane = tid & 31, wid = tid >> 5;
    const int wm = (wid & 1)*64, wn = (wid >> 1)*32;
    const int m0 = blockIdx.y*128, n0 = blockIdx.x*128;
    const int NC = K/64;

    float acc[4][4][4] = {};

    auto load = [&](int c, int s){
        uint32_t sa = sb + s*32768, sbm = sa + 16384;
        int k0 = c*64;
        #pragma unroll
        for (int l = 0; l < 4; l++){
            int idx = tid + l*256;
            int r = idx >> 3, c16 = idx & 7;
            uint32_t o = swz((uint32_t)(r*128 + c16*16));
            CPA(sa  + o, (const char*)(A + (size_t)(m0+r)*K + k0 + c16*8));
            CPA(sbm + o, (const char*)(B + (size_t)(n0+r)*K + k0 + c16*8));
        }
        CPA_COMMIT();
    };

    load(0, 0);
    for (int c = 0; c < NC; c++){
        int s = c & 1;
        if (c+1 < NC) load(c+1, 1-s);
        if (c+1 < NC) CPA_WAIT1(); else CPA_WAIT0();
        __syncthreads();
        uint32_t sa = sb + s*32768, sbm = sa + 16384;
        #pragma unroll
        for (int ks = 0; ks < 4; ks++){
            uint32_t a[4][4];
            #pragma unroll
            for (int mt = 0; mt < 4; mt++)
                ldsm4(a[mt][0], a[mt][1], a[mt][2], a[mt][3],
                      sa + swz((uint32_t)((wm + mt*16 + (lane & 15))*128 + (ks*16 + ((lane >> 4) << 3))*2)));
            #pragma unroll
            for (int np = 0; np < 2; np++){
                uint32_t b0, b1, b2, b3;
                int n  = wn + np*16 + ((lane >> 4) << 3) + (lane & 7);
                int kh2 = ks*16 + ((lane >> 3) & 1)*8;
                ldsm4(b0, b1, b2, b3, sbm + swz((uint32_t)(n*128 + kh2*2)));
                #pragma unroll
                for (int mt = 0; mt < 4; mt++){
                    mma16816(acc[mt][np*2],   a[mt][0], a[mt][1], a[mt][2], a[mt][3], b0, b1);
                    mma16816(acc[mt][np*2+1], a[mt][0], a[mt][1], a[mt][2], a[mt][3], b2, b3);
                }
            }
        }
        __syncthreads();
    }

    if (MODE == 0){
        #pragma unroll
        for (int mt = 0; mt < 4; mt++){
            int row = m0 + wm + mt*16 + (lane >> 2);
            #pragma unroll
            for (int nt = 0; nt < 4; nt++){
                int col = n0 + wn + nt*8 + 2*(lane & 3);
                float2 bi = *(const float2*)&bias[col];
                float2 o0 = { acc[mt][nt][0] + bi.x, acc[mt][nt][1] + bi.y };
                float2 o1 = { acc[mt][nt][2] + bi.x, acc[mt][nt][3] + bi.y };
                *(float2*)&C[(size_t)row*N + col]     = o0;
                *(float2*)&C[(size_t)(row+8)*N + col] = o1;
            }
        }
    } else {
        const int b  = m0 >> 11;          // /SS
        const int s0 = m0 & 2047;
        const int region = n0 / DM;       // 0=q 1=k 2=v
        const int h0 = (n0 % DM) >> 6;    // first of the two heads in this tile
        if (region < 2){
            const float sc = (region == 0) ? 0.125f : 1.f;
            __half* dst = (region == 0) ? qh : kh;
            #pragma unroll
            for (int mt = 0; mt < 4; mt++){
                int r = wm + mt*16 + (lane >> 2);
                #pragma unroll
                for (int nt = 0; nt < 4; nt++){
                    int cl = wn + nt*8 + 2*(lane & 3);
                    float2 bi = *(const float2*)&bias[n0 + cl];
                    int h = h0 + (cl >> 6), d = cl & 63;
                    size_t a0 = ((size_t)(b*NH + h)*SS + s0 + r)*64 + d;
                    *(uint32_t*)&dst[a0]          = pack2((acc[mt][nt][0]+bi.x)*sc, (acc[mt][nt][1]+bi.y)*sc);
                    *(uint32_t*)&dst[a0 + 8*64]   = pack2((acc[mt][nt][2]+bi.x)*sc, (acc[mt][nt][3]+bi.y)*sc);
                }
            }
        } else {
            // transpose through smem (pipeline buffers are free now): st[col][row], row-pad 136
            __half* st = (__half*)sm;
            #pragma unroll
            for (int mt = 0; mt < 4; mt++){
                int r = wm + mt*16 + (lane >> 2);
                #pragma unroll
                for (int nt = 0; nt < 4; nt++){
                    int cl = wn + nt*8 + 2*(lane & 3);
                    float2 bi = *(const float2*)&bias[n0 + cl];
                    st[(cl+0)*136 + r]     = __float2half_rn(acc[mt][nt][0] + bi.x);
                    st[(cl+1)*136 + r]     = __float2half_rn(acc[mt][nt][1] + bi.y);
                    st[(cl+0)*136 + r + 8] = __float2half_rn(acc[mt][nt][2] + bi.x);
                    st[(cl+1)*136 + r + 8] = __float2half_rn(acc[mt][nt][3] + bi.y);
                }
            }
            __syncthreads();
            #pragma unroll
            for (int l = 0; l < 8; l++){
                int idx = tid + l*256;
                int d = idx >> 4, rc = idx & 15;
                uint4 v = *(const uint4*)&st[d*136 + rc*8];
                int h = h0 + (d >> 6), dl = d & 63;
                *(uint4*)&vt[((size_t)(b*NH + h)*64 + dl)*SS + s0 + rc*8] = v;
            }
        }
    }
}

// ---------------- attention: CTA = (128-query tile, bh); 8 warps x 16 q-rows ----------------
__global__ __launch_bounds__(256, 2)
void attn_h(const __half* __restrict__ Q, const __half* __restrict__ Kh,
            const __half* __restrict__ Vt, __half* __restrict__ av)
{
    extern __shared__ char sm[];
    const uint32_t sb = smem_u32(sm);
    const uint32_t SQ = sb;            // 16KB
    const uint32_t SK = sb + 16384;    // 2 x 16KB
    const uint32_t SV = sb + 49152;    // 2 x 16KB (each stage: two 8KB 64-key halves)
    const int tid = threadIdx.x, lane = tid & 31, wid = tid >> 5;
    const int q0 = blockIdx.x*128, bh = blockIdx.y;
    const __half* Qp = Q  + (size_t)bh*SS*64 + (size_t)q0*64;
    const __half* Kp = Kh + (size_t)bh*SS*64;
    const __half* Vp = Vt + (size_t)bh*64*SS;

    #pragma unroll
    for (int l = 0; l < 4; l++){
        int idx = tid + l*256; int r = idx >> 3, c = idx & 7;
        uint32_t o = swz((uint32_t)(r*128 + c*16));
        CPA(SQ + o, (const char*)(Qp + r*64 + c*8));
        CPA(SK + o, (const char*)(Kp + r*64 + c*8));
    }
    #pragma unroll
    for (int l = 0; l < 4; l++){
        int idx = tid + l*256; int d = idx >> 4, c = idx & 15;
        CPA(SV + (c >> 3)*8192 + swz((uint32_t)(d*128 + (c & 7)*16)), (const char*)(Vp + (size_t)d*SS + c*8));
    }
    CPA_COMMIT();

    float o[8][4] = {};
    float rs0 = 0.f, rs1 = 0.f;
    uint32_t qf[4][4];
    bool qloaded = false;

    for (int t = 0; t < 16; t++){
        int s = t & 1;
        if (t+1 < 16){
            const __half* Kn = Kp + (size_t)(t+1)*128*64;
            #pragma unroll
            for (int l = 0; l < 4; l++){
                int idx = tid + l*256; int r = idx >> 3, c = idx & 7;
                CPA(SK + (1-s)*16384 + swz((uint32_t)(r*128 + c*16)), (const char*)(Kn + r*64 + c*8));
            }
            #pragma unroll
            for (int l = 0; l < 4; l++){
                int idx = tid + l*256; int d = idx >> 4, c = idx & 15;
                CPA(SV + (1-s)*16384 + (c >> 3)*8192 + swz((uint32_t)(d*128 + (c & 7)*16)),
                    (const char*)(Vp + (size_t)d*SS + (t+1)*128 + c*8));
            }
            CPA_COMMIT();
            CPA_WAIT1();
        } else CPA_WAIT0();
        __syncthreads();

        if (!qloaded){
            #pragma unroll
            for (int ks = 0; ks < 4; ks++)
                ldsm4(qf[ks][0], qf[ks][1], qf[ks][2], qf[ks][3],
                      SQ + swz((uint32_t)((wid*16 + (lane & 15))*128 + (ks*16 + ((lane >> 4) << 3))*2)));
            qloaded = true;
        }

        uint32_t sk = SK + s*16384, sv = SV + s*16384;
        #pragma unroll
        for (int np = 0; np < 8; np++){
            float sacc[2][4] = {};
            #pragma unroll
            for (int ks = 0; ks < 4; ks++){
                uint32_t b0, b1, b2, b3;
                int n  = np*16 + ((lane >> 4) << 3) + (lane & 7);
                int kh = ks*16 + ((lane >> 3) & 1)*8;
                ldsm4(b0, b1, b2, b3, sk + swz((uint32_t)(n*128 + kh*2)));
                mma16816(sacc[0], qf[ks][0], qf[ks][1], qf[ks][2], qf[ks][3], b0, b1);
                mma16816(sacc[1], qf[ks][0], qf[ks][1], qf[ks][2], qf[ks][3], b2, b3);
            }
            float e00 = __expf(sacc[0][0]), e01 = __expf(sacc[0][1]);
            float e02 = __expf(sacc[0][2]), e03 = __expf(sacc[0][3]);
            float e10 = __expf(sacc[1][0]), e11 = __expf(sacc[1][1]);
            float e12 = __expf(sacc[1][2]), e13 = __expf(sacc[1][3]);
            rs0 += e00 + e01 + e10 + e11;
            rs1 += e02 + e03 + e12 + e13;
            uint32_t p0 = pack2(e00, e01), p1 = pack2(e02, e03);
            uint32_t p2 = pack2(e10, e11), p3 = pack2(e12, e13);
            #pragma unroll
            for (int dp = 0; dp < 4; dp++){
                uint32_t b0, b1, b2, b3;
                int d   = dp*16 + ((lane >> 4) << 3) + (lane & 7);
                int key = np*16 + ((lane >> 3) & 1)*8;
                ldsm4(b0, b1, b2, b3, sv + (key >> 6)*8192 + swz((uint32_t)(d*128 + (key & 63)*2)));
                mma16816(o[dp*2],   p0, p1, p2, p3, b0, b1);
                mma16816(o[dp*2+1], p0, p1, p2, p3, b2, b3);
            }
        }
        __syncthreads();
    }

    rs0 += __shfl_xor_sync(~0u, rs0, 1); rs0 += __shfl_xor_sync(~0u, rs0, 2);
    rs1 += __shfl_xor_sync(~0u, rs1, 1); rs1 += __shfl_xor_sync(~0u, rs1, 2);
    float i0 = 1.f/rs0, i1 = 1.f/rs1;
    int b = bh / NH, h = bh % NH;
    int qrow = q0 + wid*16 + (lane >> 2);
    #pragma unroll
    for (int dt = 0; dt < 8; dt++){
        int col = h*64 + dt*8 + 2*(lane & 3);
        *(uint32_t*)&av[(size_t)(b*SS + qrow)*DM + col]     = pack2(o[dt][0]*i0, o[dt][1]*i0);
        *(uint32_t*)&av[(size_t)(b*SS + qrow + 8)*DM + col] = pack2(o[dt][2]*i1, o[dt][3]*i1);
    }
}

// ---------------- residual + scalar-affine norm ----------------
__device__ __forceinline__ float block_sum256(float v, float* red){
    int lane = threadIdx.x & 31, w = threadIdx.x >> 5;
    #pragma unroll
    for (int m = 16; m > 0; m >>= 1) v += __shfl_xor_sync(0xffffffffu, v, m);
    if (lane == 0) red[w] = v;
    __syncthreads();
    if (w == 0){
        float t = (lane < 8) ? red[lane] : 0.f;
        #pragma unroll
        for (int m = 4; m > 0; m >>= 1) t += __shfl_xor_sync(0xffffffffu, t, m);
        if (lane == 0) red[0] = t;
    }
    __syncthreads();
    float r = red[0];
    __syncthreads();
    return r;
}

template<bool RELU, bool EMIT>
__global__ __launch_bounds__(256)
void norm_kernel(const float* __restrict__ x1, const float* __restrict__ x2,
                 const float* __restrict__ scale, const float* __restrict__ bias,
                 float* __restrict__ out, __half* __restrict__ oh)
{
    __shared__ float red[32];
    const size_t row = blockIdx.x;
    const int tid = threadIdx.x;
    const float* p1 = x1 + row*DM;
    const float* p2 = x2 + row*DM;
    float v[3], s = 0.f;
    #pragma unroll
    for (int l = 0; l < 3; l++){
        float a = p1[tid + l*256];
        if (RELU) a = fmaxf(a, 0.f);
        v[l] = a + p2[tid + l*256];
        s += v[l];
    }
    float mean = block_sum256(s, red) * (1.f/DM);
    float sq = 0.f;
    #pragma unroll
    for (int l = 0; l < 3; l++){ float d = v[l] - mean; sq += d*d; }
    float inv_std = rsqrtf(block_sum256(sq, red) * (1.f/DM));
    float sc = scale[0], bi = bias[0];
    #pragma unroll
    for (int l = 0; l < 3; l++){
        float o = (v[l] - mean) * inv_std * sc + bi;
        size_t a = row*DM + tid + l*256;
        out[a] = o;
        if (EMIT) oh[a] = __float2half_rn(o);
    }
}

// ---------------- launch ----------------
extern "C" void kernel_launch(void* const* d_in, const int* in_sizes, int n_in,
                              void* d_out, int out_size)
{
    const float* base = (const float*)d_in[0];
    const float* Wqkv = (const float*)d_in[1];
    const float* bqkv = (const float*)d_in[2];
    const float* W1   = (const float*)d_in[3];
    const float* b1   = (const float*)d_in[4];
    const float* W2   = (const float*)d_in[5];
    const float* b2   = (const float*)d_in[6];
    const float* n1s  = (const float*)d_in[7];
    const float* n1b  = (const float*)d_in[8];
    const float* n2s  = (const float*)d_in[9];
    const float* n2b  = (const float*)d_in[10];
    float* out = (float*)d_out;

    float *t1, *hid;
    __half *bh, *qh, *kh, *vt, *av, *hh, *wqT, *w1T, *w2T;
    cudaGetSymbolAddress((void**)&t1,  g_t1);
    cudaGetSymbolAddress((void**)&hid, g_hid);
    cudaGetSymbolAddress((void**)&bh,  g_bh);
    cudaGetSymbolAddress((void**)&qh,  g_qh);
    cudaGetSymbolAddress((void**)&kh,  g_kh);
    cudaGetSymbolAddress((void**)&vt,  g_vt);
    cudaGetSymbolAddress((void**)&av,  g_av);
    cudaGetSymbolAddress((void**)&hh,  g_hh);
    cudaGetSymbolAddress((void**)&wqT, g_wqT);
    cudaGetSymbolAddress((void**)&w1T, g_w1T);
    cudaGetSymbolAddress((void**)&w2T, g_w2T);

    cudaFuncSetAttribute(gemm_h<DM3,DM,1>, cudaFuncAttributeMaxDynamicSharedMemorySize, 65536);
    cudaFuncSetAttribute(gemm_h<DM,DM,0>,  cudaFuncAttributeMaxDynamicSharedMemorySize, 65536);
    cudaFuncSetAttribute(attn_h,           cudaFuncAttributeMaxDynamicSharedMemorySize, 81920);

    conv_base<<<2048, 256>>>(base, bh, MR*DM);
    transp_conv<<<dim3(DM3/32, DM/32), 256>>>(Wqkv, wqT, DM, DM3);
    transp_conv<<<dim3(DM/32,  DM/32), 256>>>(W1,   w1T, DM, DM);
    transp_conv<<<dim3(DM/32,  DM/32), 256>>>(W2,   w2T, DM, DM);

    gemm_h<DM3,DM,1><<<dim3(DM3/128, MR/128), 256, 65536>>>(bh, wqT, bqkv, nullptr, qh, kh, vt);
    attn_h<<<dim3(SS/128, BB*NH), 256, 81920>>>(qh, kh, vt, av);
    gemm_h<DM,DM,0><<<dim3(DM/128, MR/128), 256, 65536>>>(av, w1T, b1, t1, nullptr, nullptr, nullptr);
    norm_kernel<false, true><<<MR, 256>>>(t1, base, n1s, n1b, hid, hh);
    gemm_h<DM,DM,0><<<dim3(DM/128, MR/128), 256, 65536>>>(hh, w2T, b2, t1, nullptr, nullptr, nullptr);
    norm_kernel<true, false><<<MR, 256>>>(t1, hid, n2s, n2b, out, nullptr);
}